// round 7
// baseline (speedup 1.0000x reference)
#include <cuda_runtime.h>

// PolyConv: h = sum_k theta_k * L_sym^k x, L_sym = I - D^{-1/2} A D^{-1/2}
// N=100000 nodes, E=1600000 edges, F=64 features, 5 coefficients.
//
// Strategy: detect edge_index dtype (int32 vs int64) at runtime, normalize to
// clamped int32 (fused with degree counting), build CSR (edges grouped by dst),
// then 4 gather-based propagation kernels (warp per dst node, float2 per lane,
// 4-deep unroll, dual accumulators). Working set ~103MB < 126MB L2.

#define NN 100000
#define EE 1600000
#define FF 64

// Scratch (static __device__ arrays: allocation-free per harness rules)
__device__ int   g_is_i64;
__device__ int   g_src[EE];
__device__ int   g_dst[EE];
__device__ int   g_deg[NN];
__device__ int   g_rowptr[NN + 1];
__device__ int   g_cursor[NN];
__device__ float g_dis[NN];        // D^{-1/2} per node
__device__ int   g_col[EE];        // src ids grouped by dst
__device__ float g_feat0[(size_t)NN * FF];
__device__ float g_feat1[(size_t)NN * FF];

// Probe dtype: true-int64 values < 2^32 have all-zero high words; int32 data
// interpreted as "high words" at odd offsets is random node ids
// (P(zero) = 1e-5 per word, 4096 samples -> P(all zero) ~ 0).
// Single block of 256 threads, shared-memory OR reduction.
__global__ void detect_kernel(const unsigned int* __restrict__ w) {
    __shared__ unsigned int s_acc[256];
    unsigned int acc = 0;
    for (int i = threadIdx.x; i < 4096; i += 256) acc |= w[2 * i + 1];
    s_acc[threadIdx.x] = acc;
    __syncthreads();
    for (int off = 128; off > 0; off >>= 1) {
        if (threadIdx.x < off) s_acc[threadIdx.x] |= s_acc[threadIdx.x + off];
        __syncthreads();
    }
    if (threadIdx.x == 0) g_is_i64 = (s_acc[0] == 0) ? 1 : 0;
}

__global__ void zero_deg_kernel() {
    int i = blockIdx.x * blockDim.x + threadIdx.x;
    if (i < NN) g_deg[i] = 0;
}

// Normalize edges to clamped int32 AND count in-degrees in one pass.
__global__ void convert_count_kernel(const void* __restrict__ ei) {
    int e = blockIdx.x * blockDim.x + threadIdx.x;
    if (e >= EE) return;
    int s, d;
    if (g_is_i64) {
        const long long* p = (const long long*)ei;
        s = (int)p[e];
        d = (int)p[e + EE];
    } else {
        const int* p = (const int*)ei;
        s = p[e];
        d = p[e + EE];
    }
    // Clamp: makes OOB gathers structurally impossible even if probe is wrong.
    s = min(max(s, 0), NN - 1);
    d = min(max(d, 0), NN - 1);
    g_src[e] = s;
    g_dst[e] = d;
    atomicAdd(&g_deg[d], 1);
}

// Single-block 3-phase scan: per-thread segment sums -> block scan -> writeback.
__global__ void scan_kernel() {
    __shared__ int s_part[1024];
    int tid = threadIdx.x;
    const int chunk = (NN + 1023) / 1024;   // 98
    int lo = tid * chunk;
    int hi = lo + chunk; if (hi > NN) hi = NN;
    if (lo > NN) lo = NN;

    int sum = 0;
    for (int i = lo; i < hi; i++) sum += g_deg[i];
    s_part[tid] = sum;
    __syncthreads();

    for (int off = 1; off < 1024; off <<= 1) {
        int t = (tid >= off) ? s_part[tid - off] : 0;
        __syncthreads();
        s_part[tid] += t;
        __syncthreads();
    }
    int run = s_part[tid] - sum;  // exclusive prefix for this segment
    for (int i = lo; i < hi; i++) {
        int d = g_deg[i];
        g_rowptr[i] = run;
        g_cursor[i] = run;
        g_dis[i]    = rsqrtf((float)(d > 0 ? d : 1));
        run += d;
    }
    if (tid == 1023) g_rowptr[NN] = s_part[1023];
}

__global__ void fill_kernel() {
    int e = blockIdx.x * blockDim.x + threadIdx.x;
    if (e < EE) {
        int pos = atomicAdd(&g_cursor[g_dst[e]], 1);
        g_col[pos] = g_src[e];
    }
}

// One warp per dst node; lane owns features [2*lane, 2*lane+1] as float2.
// acc = sum_{s in N(i)} feat[s] * dis[s];  newfeat = feat[i] - dis[i]*acc;
// h += theta * newfeat  (first iter: h = 0.6*x + theta*newfeat).
__global__ void __launch_bounds__(256) prop_kernel(
    const float* __restrict__ x, float* __restrict__ h,
    int in_sel, int out_sel, float theta, int first)
{
    int gw = (blockIdx.x * blockDim.x + threadIdx.x) >> 5;
    if (gw >= NN) return;
    int lane = threadIdx.x & 31;

    const float* fin = (in_sel == 0) ? g_feat0 : (in_sel == 1) ? g_feat1 : x;
    float* fout = (out_sel == 0) ? g_feat0 : g_feat1;
    const float2* __restrict__ fin2 = (const float2*)fin;

    int start = __ldg(&g_rowptr[gw]);
    int end   = __ldg(&g_rowptr[gw + 1]);

    // Dual accumulator pairs to split the FFMA dependency chain.
    float ax0 = 0.f, ay0 = 0.f, ax1 = 0.f, ay1 = 0.f;
    int j = start;
    for (; j + 4 <= end; j += 4) {
        int s0 = __ldg(&g_col[j + 0]);
        int s1 = __ldg(&g_col[j + 1]);
        int s2 = __ldg(&g_col[j + 2]);
        int s3 = __ldg(&g_col[j + 3]);
        float2 f0 = fin2[(size_t)s0 * 32 + lane];
        float2 f1 = fin2[(size_t)s1 * 32 + lane];
        float2 f2 = fin2[(size_t)s2 * 32 + lane];
        float2 f3 = fin2[(size_t)s3 * 32 + lane];
        float d0 = __ldg(&g_dis[s0]);
        float d1 = __ldg(&g_dis[s1]);
        float d2 = __ldg(&g_dis[s2]);
        float d3 = __ldg(&g_dis[s3]);
        ax0 += f0.x * d0; ay0 += f0.y * d0;
        ax1 += f1.x * d1; ay1 += f1.y * d1;
        ax0 += f2.x * d2; ay0 += f2.y * d2;
        ax1 += f3.x * d3; ay1 += f3.y * d3;
    }
    for (; j < end; j++) {
        int s = __ldg(&g_col[j]);
        float d = __ldg(&g_dis[s]);
        float2 f = fin2[(size_t)s * 32 + lane];
        ax0 += f.x * d; ay0 += f.y * d;
    }
    float ax = ax0 + ax1;
    float ay = ay0 + ay1;

    float di = __ldg(&g_dis[gw]);
    float2 fi = fin2[(size_t)gw * 32 + lane];
    float nx = fi.x - di * ax;
    float ny = fi.y - di * ay;
    ((float2*)fout)[(size_t)gw * 32 + lane] = make_float2(nx, ny);

    float2* __restrict__ h2 = (float2*)h;
    float hx, hy;
    if (first) {
        hx = 0.6f * fi.x;   // fin == x on the first iteration
        hy = 0.6f * fi.y;
    } else {
        float2 hv = h2[(size_t)gw * 32 + lane];
        hx = hv.x; hy = hv.y;
    }
    hx += theta * nx;
    hy += theta * ny;
    h2[(size_t)gw * 32 + lane] = make_float2(hx, hy);
}

extern "C" void kernel_launch(void* const* d_in, const int* in_sizes, int n_in,
                              void* d_out, int out_size)
{
    // Identify inputs by element count (x: N*F, edge_index: 2*E), falling
    // back to positional order. Edge dtype (i32 vs i64) detected on device.
    const float* x = (const float*)d_in[0];
    const void* ei = d_in[1];
    for (int i = 0; i < n_in; i++) {
        if (in_sizes[i] == 2 * EE) ei = d_in[i];
        else if (in_sizes[i] == NN * FF) x = (const float*)d_in[i];
    }
    float* h = (float*)d_out;

    // --- dtype probe, then normalize edges + count degrees (fused) ---
    detect_kernel<<<1, 256>>>((const unsigned int*)ei);
    zero_deg_kernel<<<(NN + 255) / 256, 256>>>();
    convert_count_kernel<<<(EE + 255) / 256, 256>>>(ei);

    // --- CSR build ---
    scan_kernel<<<1, 1024>>>();
    fill_kernel<<<(EE + 255) / 256, 256>>>();

    // --- 4 propagation rounds, h fused ---
    int blocks = ((size_t)NN * 32 + 255) / 256;
    prop_kernel<<<blocks, 256>>>(x, h, 2, 0, -0.4f, 1);  // x -> feat0
    prop_kernel<<<blocks, 256>>>(x, h, 0, 1,  0.3f, 0);  // feat0 -> feat1
    prop_kernel<<<blocks, 256>>>(x, h, 1, 0, -0.2f, 0);  // feat1 -> feat0
    prop_kernel<<<blocks, 256>>>(x, h, 0, 1,  0.1f, 0);  // feat0 -> feat1
}

// round 8
// speedup vs baseline: 1.9047x; 1.9047x over previous
#include <cuda_runtime.h>

// PolyConv: h = sum_k theta_k * L_sym^k x, L_sym = I - D^{-1/2} A D^{-1/2}
// N=100000 nodes, E=1600000 edges, F=64 features, 5 coefficients.
//
// R7 post-mortem: scan_kernel (single block) was 218us of 441us. Replaced with
// a 3-kernel parallel scan (98 blocks). Everything else unchanged.

#define NN 100000
#define EE 1600000
#define FF 64
#define SCAN_BLK 1024
#define NBLKS ((NN + SCAN_BLK - 1) / SCAN_BLK)   // 98

// Scratch (static __device__ arrays: allocation-free per harness rules)
__device__ int   g_is_i64;
__device__ int   g_src[EE];
__device__ int   g_dst[EE];
__device__ int   g_deg[NN];
__device__ int   g_rowptr[NN + 1];
__device__ int   g_cursor[NN];
__device__ int   g_blocksum[NBLKS];
__device__ float g_dis[NN];        // D^{-1/2} per node
__device__ int   g_col[EE];        // src ids grouped by dst
__device__ float g_feat0[(size_t)NN * FF];
__device__ float g_feat1[(size_t)NN * FF];

// Probe dtype: true-int64 values < 2^32 have all-zero high words; int32 data
// interpreted as "high words" at odd offsets is random node ids.
__global__ void detect_kernel(const unsigned int* __restrict__ w) {
    __shared__ unsigned int s_acc[256];
    unsigned int acc = 0;
    for (int i = threadIdx.x; i < 4096; i += 256) acc |= w[2 * i + 1];
    s_acc[threadIdx.x] = acc;
    __syncthreads();
    for (int off = 128; off > 0; off >>= 1) {
        if (threadIdx.x < off) s_acc[threadIdx.x] |= s_acc[threadIdx.x + off];
        __syncthreads();
    }
    if (threadIdx.x == 0) g_is_i64 = (s_acc[0] == 0) ? 1 : 0;
}

__global__ void zero_deg_kernel() {
    int i = blockIdx.x * blockDim.x + threadIdx.x;
    if (i < NN) g_deg[i] = 0;
}

// Normalize edges to clamped int32 AND count in-degrees in one pass.
__global__ void convert_count_kernel(const void* __restrict__ ei) {
    int e = blockIdx.x * blockDim.x + threadIdx.x;
    if (e >= EE) return;
    int s, d;
    if (g_is_i64) {
        const long long* p = (const long long*)ei;
        s = (int)p[e];
        d = (int)p[e + EE];
    } else {
        const int* p = (const int*)ei;
        s = p[e];
        d = p[e + EE];
    }
    s = min(max(s, 0), NN - 1);
    d = min(max(d, 0), NN - 1);
    g_src[e] = s;
    g_dst[e] = d;
    atomicAdd(&g_deg[d], 1);
}

// --- parallel scan, 3 passes ---
// Pass A: per-block inclusive scan of degrees; local exclusive prefix out.
__global__ void __launch_bounds__(SCAN_BLK) scanA_kernel() {
    __shared__ int sh[SCAN_BLK];
    int tid = threadIdx.x;
    int i = blockIdx.x * SCAN_BLK + tid;
    int v = (i < NN) ? g_deg[i] : 0;
    sh[tid] = v;
    __syncthreads();
    for (int off = 1; off < SCAN_BLK; off <<= 1) {
        int t = (tid >= off) ? sh[tid - off] : 0;
        __syncthreads();
        sh[tid] += t;
        __syncthreads();
    }
    if (i < NN) g_rowptr[i] = sh[tid] - v;   // local exclusive prefix
    if (tid == SCAN_BLK - 1) g_blocksum[blockIdx.x] = sh[tid];
}

// Pass B: single small block scans the 98 block sums (exclusive).
__global__ void scanB_kernel() {
    __shared__ int sh[128];
    int tid = threadIdx.x;
    int v = (tid < NBLKS) ? g_blocksum[tid] : 0;
    sh[tid] = v;
    __syncthreads();
    for (int off = 1; off < 128; off <<= 1) {
        int t = (tid >= off) ? sh[tid - off] : 0;
        __syncthreads();
        sh[tid] += t;
        __syncthreads();
    }
    if (tid < NBLKS) g_blocksum[tid] = sh[tid] - v;  // exclusive
    if (tid == 0) g_rowptr[NN] = EE;  // total degree == EE by construction
}

// Pass C: add block offset; write cursor and D^{-1/2}.
__global__ void __launch_bounds__(SCAN_BLK) scanC_kernel() {
    int i = blockIdx.x * SCAN_BLK + threadIdx.x;
    if (i >= NN) return;
    int r = g_rowptr[i] + g_blocksum[blockIdx.x];
    g_rowptr[i] = r;
    g_cursor[i] = r;
    int d = g_deg[i];
    g_dis[i] = rsqrtf((float)(d > 0 ? d : 1));
}

__global__ void fill_kernel() {
    int e = blockIdx.x * blockDim.x + threadIdx.x;
    if (e < EE) {
        int pos = atomicAdd(&g_cursor[g_dst[e]], 1);
        g_col[pos] = g_src[e];
    }
}

// One warp per dst node; lane owns features [2*lane, 2*lane+1] as float2.
__global__ void __launch_bounds__(256) prop_kernel(
    const float* __restrict__ x, float* __restrict__ h,
    int in_sel, int out_sel, float theta, int first)
{
    int gw = (blockIdx.x * blockDim.x + threadIdx.x) >> 5;
    if (gw >= NN) return;
    int lane = threadIdx.x & 31;

    const float* fin = (in_sel == 0) ? g_feat0 : (in_sel == 1) ? g_feat1 : x;
    float* fout = (out_sel == 0) ? g_feat0 : g_feat1;
    const float2* __restrict__ fin2 = (const float2*)fin;

    int start = __ldg(&g_rowptr[gw]);
    int end   = __ldg(&g_rowptr[gw + 1]);

    float ax0 = 0.f, ay0 = 0.f, ax1 = 0.f, ay1 = 0.f;
    int j = start;
    for (; j + 4 <= end; j += 4) {
        int s0 = __ldg(&g_col[j + 0]);
        int s1 = __ldg(&g_col[j + 1]);
        int s2 = __ldg(&g_col[j + 2]);
        int s3 = __ldg(&g_col[j + 3]);
        float2 f0 = fin2[(size_t)s0 * 32 + lane];
        float2 f1 = fin2[(size_t)s1 * 32 + lane];
        float2 f2 = fin2[(size_t)s2 * 32 + lane];
        float2 f3 = fin2[(size_t)s3 * 32 + lane];
        float d0 = __ldg(&g_dis[s0]);
        float d1 = __ldg(&g_dis[s1]);
        float d2 = __ldg(&g_dis[s2]);
        float d3 = __ldg(&g_dis[s3]);
        ax0 += f0.x * d0; ay0 += f0.y * d0;
        ax1 += f1.x * d1; ay1 += f1.y * d1;
        ax0 += f2.x * d2; ay0 += f2.y * d2;
        ax1 += f3.x * d3; ay1 += f3.y * d3;
    }
    for (; j < end; j++) {
        int s = __ldg(&g_col[j]);
        float d = __ldg(&g_dis[s]);
        float2 f = fin2[(size_t)s * 32 + lane];
        ax0 += f.x * d; ay0 += f.y * d;
    }
    float ax = ax0 + ax1;
    float ay = ay0 + ay1;

    float di = __ldg(&g_dis[gw]);
    float2 fi = fin2[(size_t)gw * 32 + lane];
    float nx = fi.x - di * ax;
    float ny = fi.y - di * ay;
    ((float2*)fout)[(size_t)gw * 32 + lane] = make_float2(nx, ny);

    float2* __restrict__ h2 = (float2*)h;
    float hx, hy;
    if (first) {
        hx = 0.6f * fi.x;   // fin == x on the first iteration
        hy = 0.6f * fi.y;
    } else {
        float2 hv = h2[(size_t)gw * 32 + lane];
        hx = hv.x; hy = hv.y;
    }
    hx += theta * nx;
    hy += theta * ny;
    h2[(size_t)gw * 32 + lane] = make_float2(hx, hy);
}

extern "C" void kernel_launch(void* const* d_in, const int* in_sizes, int n_in,
                              void* d_out, int out_size)
{
    const float* x = (const float*)d_in[0];
    const void* ei = d_in[1];
    for (int i = 0; i < n_in; i++) {
        if (in_sizes[i] == 2 * EE) ei = d_in[i];
        else if (in_sizes[i] == NN * FF) x = (const float*)d_in[i];
    }
    float* h = (float*)d_out;

    // --- dtype probe, then normalize edges + count degrees (fused) ---
    detect_kernel<<<1, 256>>>((const unsigned int*)ei);
    zero_deg_kernel<<<(NN + 255) / 256, 256>>>();
    convert_count_kernel<<<(EE + 255) / 256, 256>>>(ei);

    // --- CSR build: parallel scan + fill ---
    scanA_kernel<<<NBLKS, SCAN_BLK>>>();
    scanB_kernel<<<1, 128>>>();
    scanC_kernel<<<NBLKS, SCAN_BLK>>>();
    fill_kernel<<<(EE + 255) / 256, 256>>>();

    // --- 4 propagation rounds, h fused ---
    int blocks = ((size_t)NN * 32 + 255) / 256;
    prop_kernel<<<blocks, 256>>>(x, h, 2, 0, -0.4f, 1);  // x -> feat0
    prop_kernel<<<blocks, 256>>>(x, h, 0, 1,  0.3f, 0);  // feat0 -> feat1
    prop_kernel<<<blocks, 256>>>(x, h, 1, 0, -0.2f, 0);  // feat1 -> feat0
    prop_kernel<<<blocks, 256>>>(x, h, 0, 1,  0.1f, 0);  // feat0 -> feat1
}

// round 9
// speedup vs baseline: 2.0875x; 1.0959x over previous
#include <cuda_runtime.h>
#include <cuda_fp16.h>

// PolyConv: h = sum_k theta_k * L_sym^k x. N=100000, E=1600000, F=64.
//
// R8 post-mortem: prop kernels are at the LTS (~12 TB/s) cap; only traffic
// reduction helps. R9: iterate in scaled space s_k = D^{-1/2} feat_k stored
// as fp16 (gather row 256B -> 128B, dis gather eliminated). fp32 accumulate,
// h path uses pre-quantization values + original fp32 x for the theta0 term.

#define NN 100000
#define EE 1600000
#define FF 64
#define SCAN_BLK 1024
#define NBLKS ((NN + SCAN_BLK - 1) / SCAN_BLK)   // 98

__device__ int   g_is_i64;
__device__ int   g_src[EE];
__device__ int   g_dst[EE];
__device__ int   g_deg[NN];
__device__ int   g_rowptr[NN + 1];
__device__ int   g_cursor[NN];
__device__ int   g_blocksum[NBLKS];
__device__ float g_dis[NN];    // d^{-1/2}
__device__ float g_dis2[NN];   // 1/d
__device__ float g_dinv[NN];   // d^{1/2}
__device__ int   g_col[EE];    // src ids grouped by dst
__device__ __align__(256) __half2 g_s0[(size_t)NN * 32];  // fp16 scaled feats
__device__ __align__(256) __half2 g_s1[(size_t)NN * 32];

// Probe dtype: true-int64 values < 2^32 have all-zero high words.
__global__ void detect_kernel(const unsigned int* __restrict__ w) {
    __shared__ unsigned int s_acc[256];
    unsigned int acc = 0;
    for (int i = threadIdx.x; i < 4096; i += 256) acc |= w[2 * i + 1];
    s_acc[threadIdx.x] = acc;
    __syncthreads();
    for (int off = 128; off > 0; off >>= 1) {
        if (threadIdx.x < off) s_acc[threadIdx.x] |= s_acc[threadIdx.x + off];
        __syncthreads();
    }
    if (threadIdx.x == 0) g_is_i64 = (s_acc[0] == 0) ? 1 : 0;
}

__global__ void zero_deg_kernel() {
    int i = blockIdx.x * blockDim.x + threadIdx.x;
    if (i < NN) g_deg[i] = 0;
}

// Normalize edges to clamped int32 AND count in-degrees in one pass.
__global__ void convert_count_kernel(const void* __restrict__ ei) {
    int e = blockIdx.x * blockDim.x + threadIdx.x;
    if (e >= EE) return;
    int s, d;
    if (g_is_i64) {
        const long long* p = (const long long*)ei;
        s = (int)p[e];
        d = (int)p[e + EE];
    } else {
        const int* p = (const int*)ei;
        s = p[e];
        d = p[e + EE];
    }
    s = min(max(s, 0), NN - 1);
    d = min(max(d, 0), NN - 1);
    g_src[e] = s;
    g_dst[e] = d;
    atomicAdd(&g_deg[d], 1);
}

// --- parallel scan, 3 passes ---
__global__ void __launch_bounds__(SCAN_BLK) scanA_kernel() {
    __shared__ int sh[SCAN_BLK];
    int tid = threadIdx.x;
    int i = blockIdx.x * SCAN_BLK + tid;
    int v = (i < NN) ? g_deg[i] : 0;
    sh[tid] = v;
    __syncthreads();
    for (int off = 1; off < SCAN_BLK; off <<= 1) {
        int t = (tid >= off) ? sh[tid - off] : 0;
        __syncthreads();
        sh[tid] += t;
        __syncthreads();
    }
    if (i < NN) g_rowptr[i] = sh[tid] - v;
    if (tid == SCAN_BLK - 1) g_blocksum[blockIdx.x] = sh[tid];
}

__global__ void scanB_kernel() {
    __shared__ int sh[128];
    int tid = threadIdx.x;
    int v = (tid < NBLKS) ? g_blocksum[tid] : 0;
    sh[tid] = v;
    __syncthreads();
    for (int off = 1; off < 128; off <<= 1) {
        int t = (tid >= off) ? sh[tid - off] : 0;
        __syncthreads();
        sh[tid] += t;
        __syncthreads();
    }
    if (tid < NBLKS) g_blocksum[tid] = sh[tid] - v;
    if (tid == 0) g_rowptr[NN] = EE;
}

__global__ void __launch_bounds__(SCAN_BLK) scanC_kernel() {
    int i = blockIdx.x * SCAN_BLK + threadIdx.x;
    if (i >= NN) return;
    int r = g_rowptr[i] + g_blocksum[blockIdx.x];
    g_rowptr[i] = r;
    g_cursor[i] = r;
    int d = g_deg[i]; if (d < 1) d = 1;
    float df = (float)d;
    g_dis[i]  = rsqrtf(df);
    g_dis2[i] = 1.0f / df;
    g_dinv[i] = sqrtf(df);
}

// s0 = fp16(D^{-1/2} x)
__global__ void prescale_kernel(const float2* __restrict__ x2) {
    int idx = blockIdx.x * blockDim.x + threadIdx.x;   // NN*32 half2 elems
    if (idx >= NN * 32) return;
    int node = idx >> 5;
    float dis = g_dis[node];
    float2 v = x2[idx];
    g_s0[idx] = __floats2half2_rn(v.x * dis, v.y * dis);
}

__global__ void fill_kernel() {
    int e = blockIdx.x * blockDim.x + threadIdx.x;
    if (e < EE) {
        int pos = atomicAdd(&g_cursor[g_dst[e]], 1);
        g_col[pos] = g_src[e];
    }
}

// One warp per dst node; lane owns features [2*lane, 2*lane+1] as half2.
// agg = sum_{src} s[src] (no scale in scaled space);
// s_new[i] = s[i] - (1/d_i) * agg;  h += theta * sqrt(d_i) * s_new (fp32).
__global__ void __launch_bounds__(256) prop_kernel(
    const float2* __restrict__ x2, float2* __restrict__ h2,
    int in_sel, float theta, int first)
{
    int gw = (blockIdx.x * blockDim.x + threadIdx.x) >> 5;
    if (gw >= NN) return;
    int lane = threadIdx.x & 31;

    const __half2* __restrict__ fin = (in_sel == 0) ? g_s0 : g_s1;
    __half2* __restrict__ fout      = (in_sel == 0) ? g_s1 : g_s0;

    int start = __ldg(&g_rowptr[gw]);
    int end   = __ldg(&g_rowptr[gw + 1]);

    float ax0 = 0.f, ay0 = 0.f, ax1 = 0.f, ay1 = 0.f;
    int j = start;
    for (; j + 4 <= end; j += 4) {
        int s0 = __ldg(&g_col[j + 0]);
        int s1 = __ldg(&g_col[j + 1]);
        int s2 = __ldg(&g_col[j + 2]);
        int s3 = __ldg(&g_col[j + 3]);
        float2 f0 = __half22float2(fin[(size_t)s0 * 32 + lane]);
        float2 f1 = __half22float2(fin[(size_t)s1 * 32 + lane]);
        float2 f2 = __half22float2(fin[(size_t)s2 * 32 + lane]);
        float2 f3 = __half22float2(fin[(size_t)s3 * 32 + lane]);
        ax0 += f0.x; ay0 += f0.y;
        ax1 += f1.x; ay1 += f1.y;
        ax0 += f2.x; ay0 += f2.y;
        ax1 += f3.x; ay1 += f3.y;
    }
    for (; j < end; j++) {
        int s = __ldg(&g_col[j]);
        float2 f = __half22float2(fin[(size_t)s * 32 + lane]);
        ax0 += f.x; ay0 += f.y;
    }
    float ax = ax0 + ax1;
    float ay = ay0 + ay1;

    float d2 = __ldg(&g_dis2[gw]);
    float dv = __ldg(&g_dinv[gw]);
    float2 si = __half22float2(fin[(size_t)gw * 32 + lane]);
    float nx = si.x - d2 * ax;
    float ny = si.y - d2 * ay;
    fout[(size_t)gw * 32 + lane] = __floats2half2_rn(nx, ny);

    float hx, hy;
    if (first) {
        float2 xv = x2[(size_t)gw * 32 + lane];   // exact fp32 theta0 term
        hx = 0.6f * xv.x;
        hy = 0.6f * xv.y;
    } else {
        float2 hv = h2[(size_t)gw * 32 + lane];
        hx = hv.x; hy = hv.y;
    }
    float tdv = theta * dv;
    hx += tdv * nx;   // pre-quantization fp32 values feed h
    hy += tdv * ny;
    h2[(size_t)gw * 32 + lane] = make_float2(hx, hy);
}

extern "C" void kernel_launch(void* const* d_in, const int* in_sizes, int n_in,
                              void* d_out, int out_size)
{
    const float* x = (const float*)d_in[0];
    const void* ei = d_in[1];
    for (int i = 0; i < n_in; i++) {
        if (in_sizes[i] == 2 * EE) ei = d_in[i];
        else if (in_sizes[i] == NN * FF) x = (const float*)d_in[i];
    }
    float2* h2 = (float2*)d_out;
    const float2* x2 = (const float2*)x;

    // --- dtype probe, normalize edges + count degrees ---
    detect_kernel<<<1, 256>>>((const unsigned int*)ei);
    zero_deg_kernel<<<(NN + 255) / 256, 256>>>();
    convert_count_kernel<<<(EE + 255) / 256, 256>>>(ei);

    // --- CSR build: parallel scan + fill; prescale x into fp16 scaled space ---
    scanA_kernel<<<NBLKS, SCAN_BLK>>>();
    scanB_kernel<<<1, 128>>>();
    scanC_kernel<<<NBLKS, SCAN_BLK>>>();
    prescale_kernel<<<(NN * 32 + 255) / 256, 256>>>(x2);
    fill_kernel<<<(EE + 255) / 256, 256>>>();

    // --- 4 propagation rounds in scaled fp16 space, h fused (fp32) ---
    int blocks = ((size_t)NN * 32 + 255) / 256;
    prop_kernel<<<blocks, 256>>>(x2, h2, 0, -0.4f, 1);  // s0 -> s1
    prop_kernel<<<blocks, 256>>>(x2, h2, 1,  0.3f, 0);  // s1 -> s0
    prop_kernel<<<blocks, 256>>>(x2, h2, 0, -0.2f, 0);  // s0 -> s1
    prop_kernel<<<blocks, 256>>>(x2, h2, 1,  0.1f, 0);  // s1 -> s0
}